// round 16
// baseline (speedup 1.0000x reference)
#include <cuda_runtime.h>
#include <cuda_fp16.h>
#include <cstdint>

// ============================================================================
// Problem constants
// ============================================================================
#define B_DIM  2
#define N_DIM  1024
#define M_DIM  256
#define D_DIM  576
#define H1_DIM 512
#define H2_DIM 256

// Scratch (allocation-free rule: __device__ globals)
// aprojh / bprojh are stored K-PERMUTED: within each 16-column block, the
// half2 pair for logical k-pair p (pairs 0..7) lives at slot (p&3)*2+(p>>2).
// Each mma-lane's two half2s (k0,k0+1),(k0+8,k0+9) are then one LDS.64.
__device__ __half g_aprojh[B_DIM * N_DIM * H1_DIM];   // fp16(a_proj), k-permuted
__device__ __half g_bprojh[B_DIM * M_DIM * H1_DIM];   // fp16(b_proj + b1), k-permuted
__device__ uint4  g_w2frag[32 * 16 * 32];             // W2  pre-packed mma B-fragments
__device__ uint4  g_w1afrag[36 * 32 * 32];            // W1a pre-packed mma B-fragments
__device__ uint4  g_w1bfrag[36 * 32 * 32];            // W1b pre-packed mma B-fragments

// storage half-index of the pair starting at even logical column c
__host__ __device__ __forceinline__ int permslot(int c) {
    int p = (c & 15) >> 1;
    return (c & ~15) + (((p & 3) * 2 + (p >> 2)) << 1);
}

// ============================================================================
// PTX helpers (base ISA — harness compiles for compute_103, no 'a' features)
// ============================================================================
__device__ __forceinline__ uint32_t smem_to_u32(const void* p) {
    uint32_t a;
    asm("{ .reg .u64 t; cvta.to.shared.u64 t, %1; cvt.u32.u64 %0, t; }" : "=r"(a) : "l"(p));
    return a;
}

__device__ __forceinline__ void cp16(uint32_t s, const void* g) {
    asm volatile("cp.async.cg.shared.global [%0], [%1], 16;" :: "r"(s), "l"(g) : "memory");
}
__device__ __forceinline__ void cp_commit() {
    asm volatile("cp.async.commit_group;" ::: "memory");
}

__device__ __forceinline__ void mma_f16(float* c, const uint32_t* a, uint32_t b0, uint32_t b1) {
    asm volatile(
        "mma.sync.aligned.m16n8k16.row.col.f32.f16.f16.f32 "
        "{%0,%1,%2,%3}, {%4,%5,%6,%7}, {%8,%9}, {%0,%1,%2,%3};"
        : "+f"(c[0]), "+f"(c[1]), "+f"(c[2]), "+f"(c[3])
        : "r"(a[0]), "r"(a[1]), "r"(a[2]), "r"(a[3]), "r"(b0), "r"(b1));
}

// h1 fragment: fp16 relu(a + b), 2 ops (HADD2 + HMAX2)
__device__ __forceinline__ uint32_t fragAB(uint32_t a, uint32_t b) {
    __half2 z = __float2half2_rn(0.0f);
    __half2 h = __hmax2(__hadd2(*(__half2*)&a, *(__half2*)&b), z);
    return *(uint32_t*)&h;
}

__device__ __forceinline__ uint32_t packh2(float2 v) {
    __half2 h = __floats2half2_rn(v.x, v.y);
    return *(uint32_t*)&h;
}

// ============================================================================
// Prep A: fragment ALL weight matrices into mma B-operand layout (fp16).
// 128 threads = 4 warps, each warp handles one jbp. Grid (36, 8, 3).
// ============================================================================
__global__ __launch_bounds__(128) void wfrag_kernel(
    const float* __restrict__ W2, const float* __restrict__ W1a,
    const float* __restrict__ W1b,
    uint4* __restrict__ w2f, uint4* __restrict__ w1af, uint4* __restrict__ w1bf)
{
    const int kb = blockIdx.x, z = blockIdx.z;
    const int wid = threadIdx.x >> 5;
    const int jbp = blockIdx.y * 4 + wid;
    const int lid = threadIdx.x & 31;
    const float* W;
    uint4* out;
    int stride, outidx;
    if (z == 0) {
        if (kb >= 32 || jbp >= 16) return;
        W = W2; out = w2f; stride = H2_DIM;
        outidx = (kb * 16 + jbp) * 32 + lid;
    } else {
        W = (z == 1) ? W1a : W1b;
        out = (z == 1) ? w1af : w1bf;
        stride = H1_DIM;
        outidx = (kb * 32 + jbp) * 32 + lid;
    }
    const int gg = lid >> 2, tg = lid & 3;
    const int k0 = kb * 16 + 2 * tg;
    const int j0 = jbp * 16 + gg;

    auto p2 = [&](int k, int j) {
        __half2 h = __floats2half2_rn(W[(size_t)k * stride + j],
                                      W[(size_t)(k + 1) * stride + j]);
        return *(uint32_t*)&h;
    };
    uint4 u;
    u.x = p2(k0, j0);
    u.y = p2(k0 + 8, j0);
    u.z = p2(k0, j0 + 8);
    u.w = p2(k0 + 8, j0 + 8);
    out[outidx] = u;
}

// ============================================================================
// Prep B: projection GEMMs on tensor cores, 3-deep register pipeline.
// ============================================================================
__global__ __launch_bounds__(128) void proj_mma_kernel(
    const float* __restrict__ PhiA, const float* __restrict__ PhiB,
    const float* __restrict__ b1,
    const uint4* __restrict__ w1af, const uint4* __restrict__ w1bf,
    __half* __restrict__ aprojh, __half* __restrict__ bprojh)
{
    const int tid = threadIdx.x;
    const int wid = tid >> 5, lid = tid & 31;
    const int g = lid >> 2, tg = lid & 3;
    const int m0 = blockIdx.x * 32;
    const bool isB = m0 >= (B_DIM * N_DIM);
    const float* X = isB ? PhiB : PhiA;
    const int mloc = isB ? m0 - B_DIM * N_DIM : m0;
    const uint4* wf = isB ? w1bf : w1af;
    const int j0 = blockIdx.y * 128 + wid * 32;
    const int jbp0 = j0 >> 4;

    const float* Xr = X + (size_t)(mloc + g) * D_DIM;

    float acc[2][4][4] = {};

    uint4 bf[3][2];
    auto ldB = [&](uint4* d, int kb) {
        const int fb = (kb * 32 + jbp0) * 32 + lid;
        d[0] = wf[fb];
        d[1] = wf[fb + 32];
    };
    float2 x[3][8];
    auto ldA = [&](float2* d, int kb) {
        const int k = kb * 16 + 2 * tg;
        d[0] = *(const float2*)(Xr + k);
        d[1] = *(const float2*)(Xr + 8 * D_DIM + k);
        d[2] = *(const float2*)(Xr + k + 8);
        d[3] = *(const float2*)(Xr + 8 * D_DIM + k + 8);
        d[4] = *(const float2*)(Xr + 16 * D_DIM + k);
        d[5] = *(const float2*)(Xr + 24 * D_DIM + k);
        d[6] = *(const float2*)(Xr + 16 * D_DIM + k + 8);
        d[7] = *(const float2*)(Xr + 24 * D_DIM + k + 8);
    };
    ldA(x[0], 0); ldB(bf[0], 0);
    ldA(x[1], 1); ldB(bf[1], 1);
    ldA(x[2], 2); ldB(bf[2], 2);

    #pragma unroll 6
    for (int kb = 0; kb < 36; kb++) {
        const int sl = kb % 3;
        uint32_t a0[4], a1[4];
        a0[0] = packh2(x[sl][0]); a0[1] = packh2(x[sl][1]);
        a0[2] = packh2(x[sl][2]); a0[3] = packh2(x[sl][3]);
        a1[0] = packh2(x[sl][4]); a1[1] = packh2(x[sl][5]);
        a1[2] = packh2(x[sl][6]); a1[3] = packh2(x[sl][7]);
        uint4 c0 = bf[sl][0], c1 = bf[sl][1];

        if (kb < 33) { ldA(x[sl], kb + 3); ldB(bf[sl], kb + 3); }

        mma_f16(acc[0][0], a0, c0.x, c0.y);
        mma_f16(acc[0][1], a0, c0.z, c0.w);
        mma_f16(acc[1][0], a1, c0.x, c0.y);
        mma_f16(acc[1][1], a1, c0.z, c0.w);
        mma_f16(acc[0][2], a0, c1.x, c1.y);
        mma_f16(acc[0][3], a0, c1.z, c1.w);
        mma_f16(acc[1][2], a1, c1.x, c1.y);
        mma_f16(acc[1][3], a1, c1.z, c1.w);
    }

    __half* outb = isB ? (bprojh + (size_t)mloc * H1_DIM)
                       : (aprojh + (size_t)m0 * H1_DIM);
    #pragma unroll
    for (int mt = 0; mt < 2; mt++) {
        __half* orow0 = outb + (size_t)(mt * 16 + g) * H1_DIM;
        __half* orow1 = orow0 + 8 * H1_DIM;
        #pragma unroll
        for (int nt = 0; nt < 4; nt++) {
            const int j = j0 + nt * 8 + 2 * tg;
            const int sl = permslot(j);
            float v0 = acc[mt][nt][0], v1 = acc[mt][nt][1];
            float v2 = acc[mt][nt][2], v3 = acc[mt][nt][3];
            if (isB) {
                const float ba = b1[j], bb = b1[j + 1];
                v0 += ba; v1 += bb; v2 += ba; v3 += bb;
            }
            *(__half2*)&orow0[sl] = __floats2half2_rn(v0, v1);
            *(__half2*)&orow1[sl] = __floats2half2_rn(v2, v3);
        }
    }
}

// ============================================================================
// Main fused kernel — 4n x 64m tiles, bp slab resident; LOOP-INTERCHANGED:
//   outer j-chunk (4 x 64j), inner kb, innermost n(4). B-fragments + bp LDS
//   are loaded once per kb and shared across all 4 n -> W2 L2 traffic /4.
//   128 threads, 4 warps = 2 m-bands x 2 j-bands (32j per warp per chunk).
//   acc[4n][8][4] = 128 regs; B-frag double buffer only 16 regs.
//   Per-chunk results fold into 16 running partials; single s_part
//   reduction at the end (2 barriers per tile total).
// ============================================================================
#define SM_BP    0
#define SM_AROW  81920
#define SM_B2    86016
#define SM_W3    87040
#define SM_PART  88064
#define SMEM_MAIN (88064 + 2048)

__global__ __launch_bounds__(128, 2) void pair_mlp_main(
    const __half* __restrict__ aprojh, const __half* __restrict__ bprojh,
    const uint4* __restrict__ w2f, const float* __restrict__ b2,
    const float* __restrict__ w3, const float* __restrict__ b3,
    float* __restrict__ out)
{
    extern __shared__ __align__(16) char smem[];
    __half* s_bp   = (__half*)(smem + SM_BP);    // [stage][row][80]
    __half* s_arow = (__half*)(smem + SM_AROW);  // [4][512]
    float*  s_b2   = (float*)(smem + SM_B2);
    float*  s_w3   = (float*)(smem + SM_W3);
    float*  s_part = (float*)(smem + SM_PART);   // [4n][64 rows][2 wc]

    const int tid = threadIdx.x;
    const int wid = tid >> 5;
    const int lid = tid & 31;
    const int wr  = wid >> 1;   // m band: rows wr*32 (0..1)
    const int wc  = wid & 1;    // j band within chunk: cols wc*32
    const int g   = lid >> 2;
    const int tg  = lid & 3;

    const int T  = blockIdx.x;            // 0..2047
    const int ng = T >> 2;                // n-group (4 n each)
    const int m0 = (T & 3) * 64;
    const int n0g = ng * 4;               // global row in (b*N+n) space
    const int b  = n0g >> 10;             // batch
    const __half* bpg = bprojh + (size_t)(b * M_DIM + m0) * H1_DIM;
    const __half* apg = aprojh + (size_t)n0g * H1_DIM;

    // ---- cp.async: full bp slab (64 rows x 512 halves -> 8 stages x 80) ----
    {
        const uint32_t sb = smem_to_u32(s_bp);
        #pragma unroll
        for (int i = 0; i < 32; i++) {
            int idx = tid + i * 128;              // 0..4095
            int st  = idx >> 9;
            int row = (idx >> 3) & 63;
            int c   = idx & 7;
            cp16(sb + st * 10240 + row * 160 + c * 16,
                 bpg + (size_t)row * H1_DIM + st * 64 + c * 8);
        }
        const uint32_t sa = smem_to_u32(s_arow);
        #pragma unroll
        for (int i = 0; i < 2; i++) {
            int idx = tid + i * 128;              // 0..255
            int p = idx >> 6, c = idx & 63;
            cp16(sa + p * 1024 + c * 16, apg + (size_t)p * H1_DIM + c * 8);
        }
        cp_commit();
    }
    s_b2[tid] = b2[tid];   s_b2[tid + 128] = b2[tid + 128];
    s_w3[tid] = w3[tid];   s_w3[tid + 128] = w3[tid + 128];

    const int r0 = wr * 32 + g;   // warp rows: r0, r0+8, r0+16, r0+24

    // B-fragment register double buffer: 2 uint4 per lane (32 j per warp)
    uint4 bfa[2], bfb[2];
    auto ldB = [&](uint4* dst, int chunk, int kb) {
        const int fb = (kb * 16 + chunk * 4 + wc * 2) * 32 + lid;
        dst[0] = w2f[fb];
        dst[1] = w2f[fb + 32];
    };
    ldB(bfa, 0, 0);

    float part[4][4];
    #pragma unroll
    for (int n = 0; n < 4; n++)
        #pragma unroll
        for (int q = 0; q < 4; q++) part[n][q] = 0.0f;

    asm volatile("cp.async.wait_group 0;" ::: "memory");
    __syncthreads();

    #pragma unroll 1
    for (int chunk = 0; chunk < 4; chunk++) {
        float acc[4][8][4];
        #pragma unroll
        for (int n = 0; n < 4; n++)
            #pragma unroll
            for (int nt = 0; nt < 8; nt++)
                #pragma unroll
                for (int q = 0; q < 4; q++) acc[n][nt][q] = 0.0f;

        #pragma unroll 8
        for (int kb = 0; kb < 32; kb++) {
            uint4* cur = (kb & 1) ? bfb : bfa;
            uint4* nxt = (kb & 1) ? bfa : bfb;
            // prefetch; at kb==31 chain into the next chunk (chunk 3: benign)
            if (kb < 31) ldB(nxt, chunk, kb + 1);
            else         ldB(nxt, (chunk < 3) ? chunk + 1 : 0, 0);

            // ---- shared bp LDS for this kb (used by all 4 n) ----
            const int st = kb >> 2;
            const int ko = (kb & 3) * 16 + tg * 4;
            const __half* bps = s_bp + st * 5120 + ko;
            const uint2 u0 = *(const uint2*)&bps[(r0     ) * 80];
            const uint2 u1 = *(const uint2*)&bps[(r0 +  8) * 80];
            const uint2 u2 = *(const uint2*)&bps[(r0 + 16) * 80];
            const uint2 u3 = *(const uint2*)&bps[(r0 + 24) * 80];
            const int ka = kb * 16 + tg * 4;

            #pragma unroll
            for (int n = 0; n < 4; n++) {
                const uint2 ua = *(const uint2*)&s_arow[n * 512 + ka];
                uint32_t a0[4], a1[4];
                a0[0] = fragAB(ua.x, u0.x);
                a0[1] = fragAB(ua.x, u1.x);
                a0[2] = fragAB(ua.y, u0.y);
                a0[3] = fragAB(ua.y, u1.y);
                a1[0] = fragAB(ua.x, u2.x);
                a1[1] = fragAB(ua.x, u3.x);
                a1[2] = fragAB(ua.y, u2.y);
                a1[3] = fragAB(ua.y, u3.y);

                #pragma unroll
                for (int q = 0; q < 2; q++) {
                    mma_f16(acc[n][q * 2 + 0], a0, cur[q].x, cur[q].y);
                    mma_f16(acc[n][q * 2 + 1], a0, cur[q].z, cur[q].w);
                    mma_f16(acc[n][4 + q * 2 + 0], a1, cur[q].x, cur[q].y);
                    mma_f16(acc[n][4 + q * 2 + 1], a1, cur[q].z, cur[q].w);
                }
            }
        }

        // ---- fold this chunk's 64 j into the running partials ----
        const int jw = chunk * 64 + wc * 32;
        #pragma unroll
        for (int nt = 0; nt < 4; nt++) {
            const int j = jw + nt * 8 + 2 * tg;
            const float b2a = s_b2[j], b2b = s_b2[j + 1];
            const float w3a = s_w3[j], w3b = s_w3[j + 1];
            #pragma unroll
            for (int n = 0; n < 4; n++) {
                const float* c0 = acc[n][nt];       // rows r0, r0+8
                const float* c1 = acc[n][4 + nt];   // rows r0+16, r0+24
                part[n][0] += fmaxf(c0[0] + b2a, 0.0f) * w3a + fmaxf(c0[1] + b2b, 0.0f) * w3b;
                part[n][1] += fmaxf(c0[2] + b2a, 0.0f) * w3a + fmaxf(c0[3] + b2b, 0.0f) * w3b;
                part[n][2] += fmaxf(c1[0] + b2a, 0.0f) * w3a + fmaxf(c1[1] + b2b, 0.0f) * w3b;
                part[n][3] += fmaxf(c1[2] + b2a, 0.0f) * w3a + fmaxf(c1[3] + b2b, 0.0f) * w3b;
            }
        }
    }

    // ---- final reduction: shfl over tg, s_part, one barrier, store ----
    #pragma unroll
    for (int n = 0; n < 4; n++)
        #pragma unroll
        for (int q = 0; q < 4; q++) {
            #pragma unroll
            for (int off = 1; off < 4; off <<= 1)
                part[n][q] += __shfl_xor_sync(0xffffffffu, part[n][q], off);
        }
    if (tg == 0) {
        #pragma unroll
        for (int n = 0; n < 4; n++) {
            s_part[n * 128 + (r0     ) * 2 + wc] = part[n][0];
            s_part[n * 128 + (r0 +  8) * 2 + wc] = part[n][1];
            s_part[n * 128 + (r0 + 16) * 2 + wc] = part[n][2];
            s_part[n * 128 + (r0 + 24) * 2 + wc] = part[n][3];
        }
    }
    __syncthreads();
    {
        const float bias3 = b3[0];
        #pragma unroll
        for (int i = 0; i < 2; i++) {
            int idx = tid + i * 128;          // 0..255 = n*64 + row
            int n = idx >> 6, row = idx & 63;
            float v = s_part[n * 128 + row * 2 + 0]
                    + s_part[n * 128 + row * 2 + 1] + bias3;
            out[(size_t)(n0g + n) * M_DIM + m0 + row] = v;
        }
    }
}

// ============================================================================
// Launch
// ============================================================================
extern "C" void kernel_launch(void* const* d_in, const int* in_sizes, int n_in,
                              void* d_out, int out_size) {
    const float* PhiA = (const float*)d_in[0];
    const float* PhiB = (const float*)d_in[1];
    const float* W1a  = (const float*)d_in[2];
    const float* W1b  = (const float*)d_in[3];
    const float* b1   = (const float*)d_in[4];
    const float* W2   = (const float*)d_in[5];
    const float* b2   = (const float*)d_in[6];
    const float* W3   = (const float*)d_in[7];
    const float* b3   = (const float*)d_in[8];
    float* out = (float*)d_out;

    __half* aprojh = nullptr;
    __half* bprojh = nullptr;
    uint4 *w2f = nullptr, *w1af = nullptr, *w1bf = nullptr;
    cudaGetSymbolAddress((void**)&aprojh, g_aprojh);
    cudaGetSymbolAddress((void**)&bprojh, g_bprojh);
    cudaGetSymbolAddress((void**)&w2f, g_w2frag);
    cudaGetSymbolAddress((void**)&w1af, g_w1afrag);
    cudaGetSymbolAddress((void**)&w1bf, g_w1bfrag);

    // fragment all weight matrices (W2, W1a, W1b)
    wfrag_kernel<<<dim3(36, 8, 3), 128>>>(W2, W1a, W1b, w2f, w1af, w1bf);
    // tensor-core projections -> k-permuted fp16 aproj/bproj
    proj_mma_kernel<<<dim3((B_DIM * N_DIM + B_DIM * M_DIM) / 32, H1_DIM / 128), 128>>>(
        PhiA, PhiB, b1, w1af, w1bf, aprojh, bprojh);
    // fused pairwise MLP (4n x 64m tiles, resident bp slab, j-chunked)
    cudaFuncSetAttribute(pair_mlp_main, cudaFuncAttributeMaxDynamicSharedMemorySize,
                         SMEM_MAIN);
    pair_mlp_main<<<B_DIM * N_DIM * M_DIM / (4 * 64), 128, SMEM_MAIN>>>(
        aprojh, bprojh, w2f, b2, W3, b3, out);
}

// round 17
// speedup vs baseline: 1.0840x; 1.0840x over previous
#include <cuda_runtime.h>
#include <cuda_fp16.h>
#include <cstdint>

// ============================================================================
// Problem constants
// ============================================================================
#define B_DIM  2
#define N_DIM  1024
#define M_DIM  256
#define D_DIM  576
#define H1_DIM 512
#define H2_DIM 256

// Scratch (allocation-free rule: __device__ globals)
// aprojh / bprojh are stored K-PERMUTED: within each 16-column block, the
// half2 pair for logical k-pair p (pairs 0..7) lives at slot (p&3)*2+(p>>2).
// Each mma-lane's two half2s (k0,k0+1),(k0+8,k0+9) are then one LDS.64.
__device__ __half g_aprojh[B_DIM * N_DIM * H1_DIM];   // fp16(a_proj), k-permuted
__device__ __half g_bprojh[B_DIM * M_DIM * H1_DIM];   // fp16(b_proj + b1), k-permuted
__device__ uint4  g_w2frag[32 * 16 * 32];             // W2  pre-packed mma B-fragments
__device__ uint4  g_w1afrag[36 * 32 * 32];            // W1a pre-packed mma B-fragments
__device__ uint4  g_w1bfrag[36 * 32 * 32];            // W1b pre-packed mma B-fragments

// storage half-index of the pair starting at even logical column c
__host__ __device__ __forceinline__ int permslot(int c) {
    int p = (c & 15) >> 1;
    return (c & ~15) + (((p & 3) * 2 + (p >> 2)) << 1);
}

// ============================================================================
// PTX helpers (base ISA — harness compiles for compute_103, no 'a' features)
// ============================================================================
__device__ __forceinline__ uint32_t smem_to_u32(const void* p) {
    uint32_t a;
    asm("{ .reg .u64 t; cvta.to.shared.u64 t, %1; cvt.u32.u64 %0, t; }" : "=r"(a) : "l"(p));
    return a;
}

__device__ __forceinline__ void cp16(uint32_t s, const void* g) {
    asm volatile("cp.async.cg.shared.global [%0], [%1], 16;" :: "r"(s), "l"(g) : "memory");
}
__device__ __forceinline__ void cp_commit() {
    asm volatile("cp.async.commit_group;" ::: "memory");
}
template <int N>
__device__ __forceinline__ void cp_wait() {
    asm volatile("cp.async.wait_group %0;" :: "n"(N) : "memory");
}

__device__ __forceinline__ void mma_f16(float* c, const uint32_t* a, uint32_t b0, uint32_t b1) {
    asm volatile(
        "mma.sync.aligned.m16n8k16.row.col.f32.f16.f16.f32 "
        "{%0,%1,%2,%3}, {%4,%5,%6,%7}, {%8,%9}, {%0,%1,%2,%3};"
        : "+f"(c[0]), "+f"(c[1]), "+f"(c[2]), "+f"(c[3])
        : "r"(a[0]), "r"(a[1]), "r"(a[2]), "r"(a[3]), "r"(b0), "r"(b1));
}

// h1 fragment: fp16 relu(a + b), 2 ops (HADD2 + HMAX2)
__device__ __forceinline__ uint32_t fragAB(uint32_t a, uint32_t b) {
    __half2 z = __float2half2_rn(0.0f);
    __half2 h = __hmax2(__hadd2(*(__half2*)&a, *(__half2*)&b), z);
    return *(uint32_t*)&h;
}

__device__ __forceinline__ uint32_t packh2(float2 v) {
    __half2 h = __floats2half2_rn(v.x, v.y);
    return *(uint32_t*)&h;
}

// ============================================================================
// Prep A: fragment ALL weight matrices into mma B-operand layout (fp16).
// 128 threads = 4 warps, each warp handles one jbp. Grid (36, 8, 3).
// ============================================================================
__global__ __launch_bounds__(128) void wfrag_kernel(
    const float* __restrict__ W2, const float* __restrict__ W1a,
    const float* __restrict__ W1b,
    uint4* __restrict__ w2f, uint4* __restrict__ w1af, uint4* __restrict__ w1bf)
{
    const int kb = blockIdx.x, z = blockIdx.z;
    const int wid = threadIdx.x >> 5;
    const int jbp = blockIdx.y * 4 + wid;
    const int lid = threadIdx.x & 31;
    const float* W;
    uint4* out;
    int stride, outidx;
    if (z == 0) {
        if (kb >= 32 || jbp >= 16) return;
        W = W2; out = w2f; stride = H2_DIM;
        outidx = (kb * 16 + jbp) * 32 + lid;
    } else {
        W = (z == 1) ? W1a : W1b;
        out = (z == 1) ? w1af : w1bf;
        stride = H1_DIM;
        outidx = (kb * 32 + jbp) * 32 + lid;
    }
    const int gg = lid >> 2, tg = lid & 3;
    const int k0 = kb * 16 + 2 * tg;
    const int j0 = jbp * 16 + gg;

    auto p2 = [&](int k, int j) {
        __half2 h = __floats2half2_rn(W[(size_t)k * stride + j],
                                      W[(size_t)(k + 1) * stride + j]);
        return *(uint32_t*)&h;
    };
    uint4 u;
    u.x = p2(k0, j0);
    u.y = p2(k0 + 8, j0);
    u.z = p2(k0, j0 + 8);
    u.w = p2(k0 + 8, j0 + 8);
    out[outidx] = u;
}

// ============================================================================
// Prep B: projection GEMMs on tensor cores, 3-deep register pipeline.
// ============================================================================
__global__ __launch_bounds__(128) void proj_mma_kernel(
    const float* __restrict__ PhiA, const float* __restrict__ PhiB,
    const float* __restrict__ b1,
    const uint4* __restrict__ w1af, const uint4* __restrict__ w1bf,
    __half* __restrict__ aprojh, __half* __restrict__ bprojh)
{
    const int tid = threadIdx.x;
    const int wid = tid >> 5, lid = tid & 31;
    const int g = lid >> 2, tg = lid & 3;
    const int m0 = blockIdx.x * 32;
    const bool isB = m0 >= (B_DIM * N_DIM);
    const float* X = isB ? PhiB : PhiA;
    const int mloc = isB ? m0 - B_DIM * N_DIM : m0;
    const uint4* wf = isB ? w1bf : w1af;
    const int j0 = blockIdx.y * 128 + wid * 32;
    const int jbp0 = j0 >> 4;

    const float* Xr = X + (size_t)(mloc + g) * D_DIM;

    float acc[2][4][4] = {};

    uint4 bf[3][2];
    auto ldB = [&](uint4* d, int kb) {
        const int fb = (kb * 32 + jbp0) * 32 + lid;
        d[0] = wf[fb];
        d[1] = wf[fb + 32];
    };
    float2 x[3][8];
    auto ldA = [&](float2* d, int kb) {
        const int k = kb * 16 + 2 * tg;
        d[0] = *(const float2*)(Xr + k);
        d[1] = *(const float2*)(Xr + 8 * D_DIM + k);
        d[2] = *(const float2*)(Xr + k + 8);
        d[3] = *(const float2*)(Xr + 8 * D_DIM + k + 8);
        d[4] = *(const float2*)(Xr + 16 * D_DIM + k);
        d[5] = *(const float2*)(Xr + 24 * D_DIM + k);
        d[6] = *(const float2*)(Xr + 16 * D_DIM + k + 8);
        d[7] = *(const float2*)(Xr + 24 * D_DIM + k + 8);
    };
    ldA(x[0], 0); ldB(bf[0], 0);
    ldA(x[1], 1); ldB(bf[1], 1);
    ldA(x[2], 2); ldB(bf[2], 2);

    #pragma unroll 6
    for (int kb = 0; kb < 36; kb++) {
        const int sl = kb % 3;
        uint32_t a0[4], a1[4];
        a0[0] = packh2(x[sl][0]); a0[1] = packh2(x[sl][1]);
        a0[2] = packh2(x[sl][2]); a0[3] = packh2(x[sl][3]);
        a1[0] = packh2(x[sl][4]); a1[1] = packh2(x[sl][5]);
        a1[2] = packh2(x[sl][6]); a1[3] = packh2(x[sl][7]);
        uint4 c0 = bf[sl][0], c1 = bf[sl][1];

        if (kb < 33) { ldA(x[sl], kb + 3); ldB(bf[sl], kb + 3); }

        mma_f16(acc[0][0], a0, c0.x, c0.y);
        mma_f16(acc[0][1], a0, c0.z, c0.w);
        mma_f16(acc[1][0], a1, c0.x, c0.y);
        mma_f16(acc[1][1], a1, c0.z, c0.w);
        mma_f16(acc[0][2], a0, c1.x, c1.y);
        mma_f16(acc[0][3], a0, c1.z, c1.w);
        mma_f16(acc[1][2], a1, c1.x, c1.y);
        mma_f16(acc[1][3], a1, c1.z, c1.w);
    }

    __half* outb = isB ? (bprojh + (size_t)mloc * H1_DIM)
                       : (aprojh + (size_t)m0 * H1_DIM);
    #pragma unroll
    for (int mt = 0; mt < 2; mt++) {
        __half* orow0 = outb + (size_t)(mt * 16 + g) * H1_DIM;
        __half* orow1 = orow0 + 8 * H1_DIM;
        #pragma unroll
        for (int nt = 0; nt < 4; nt++) {
            const int j = j0 + nt * 8 + 2 * tg;
            const int sl = permslot(j);
            float v0 = acc[mt][nt][0], v1 = acc[mt][nt][1];
            float v2 = acc[mt][nt][2], v3 = acc[mt][nt][3];
            if (isB) {
                const float ba = b1[j], bb = b1[j + 1];
                v0 += ba; v1 += bb; v2 += ba; v3 += bb;
            }
            *(__half2*)&orow0[sl] = __floats2half2_rn(v0, v1);
            *(__half2*)&orow1[sl] = __floats2half2_rn(v2, v3);
        }
    }
}

// ============================================================================
// Main fused kernel — R15 core (4n x 64m tiles, resident bp slab, 4 passes)
// + PIPELINED PROLOG: cp.async split into 9 commit groups (arow, then one
// per 64-k stage). Pass 0 consumes stage st after cp_wait<7-st> + barrier,
// overlapping early MMAs with in-flight staging. Passes 1-3 untouched
// (all stages proven resident by pass 0's cp_wait<0>).
// ============================================================================
#define SM_BP    0
#define SM_AROW  81920
#define SM_B2    86016
#define SM_W3    87040
#define SM_PART  88064
#define SMEM_MAIN (88064 + 1024)

__global__ __launch_bounds__(128, 2) void pair_mlp_main(
    const __half* __restrict__ aprojh, const __half* __restrict__ bprojh,
    const uint4* __restrict__ w2f, const float* __restrict__ b2,
    const float* __restrict__ w3, const float* __restrict__ b3,
    float* __restrict__ out)
{
    extern __shared__ __align__(16) char smem[];
    __half* s_bp   = (__half*)(smem + SM_BP);    // [stage][row][80]
    __half* s_arow = (__half*)(smem + SM_AROW);  // [4][512]
    float*  s_b2   = (float*)(smem + SM_B2);
    float*  s_w3   = (float*)(smem + SM_W3);
    float*  s_part = (float*)(smem + SM_PART);   // [2][128] by pass parity

    const int tid = threadIdx.x;
    const int wid = tid >> 5;
    const int lid = tid & 31;
    const int wr  = wid >> 1;   // m band: rows wr*32 (0..1)
    const int wc  = wid & 1;    // j band: cols wc*128
    const int g   = lid >> 2;
    const int tg  = lid & 3;

    const int T  = blockIdx.x;            // 0..2047
    const int ng = T >> 2;                // n-group (4 n each)
    const int m0 = (T & 3) * 64;
    const int n0g = ng * 4;               // global row in (b*N+n) space
    const int b  = n0g >> 10;             // batch
    const __half* bpg = bprojh + (size_t)(b * M_DIM + m0) * H1_DIM;
    const __half* apg = aprojh + (size_t)n0g * H1_DIM;

    // ---- cp.async prolog: 9 groups. Group 0 = 4 arows; groups 1..8 = one
    //      64-k stage of the bp slab each (64 rows x 128 B, stride-160 rows).
    {
        const uint32_t sa = smem_to_u32(s_arow);
        #pragma unroll
        for (int i = 0; i < 2; i++) {
            int idx = tid + i * 128;              // 0..255
            int p = idx >> 6, c = idx & 63;
            cp16(sa + p * 1024 + c * 16, apg + (size_t)p * H1_DIM + c * 8);
        }
        cp_commit();

        const uint32_t sb = smem_to_u32(s_bp);
        #pragma unroll
        for (int st = 0; st < 8; st++) {
            #pragma unroll
            for (int i = 0; i < 4; i++) {
                int idx = tid + i * 128;          // 0..511 within this stage
                int row = idx >> 3, c = idx & 7;  // 8 x 16B per row
                cp16(sb + st * 10240 + row * 160 + c * 16,
                     bpg + (size_t)row * H1_DIM + st * 64 + c * 8);
            }
            cp_commit();
        }
    }
    s_b2[tid] = b2[tid];   s_b2[tid + 128] = b2[tid + 128];
    s_w3[tid] = w3[tid];   s_w3[tid + 128] = w3[tid + 128];

    const int r0 = wr * 32 + g;   // warp rows: r0, r0+8, r0+16, r0+24

    // B-fragment register double buffer, prefetched by k16-slice kb
    uint4 bfa[8], bfb[8];
    auto ldB = [&](uint4* dst, int kb) {
        const int fb = (kb * 16 + wc * 8) * 32 + lid;
        #pragma unroll
        for (int p = 0; p < 8; p++) dst[p] = w2f[fb + p * 32];
    };
    ldB(bfa, 0);

    // one k16-slice of the mainloop (identical to R15's kb body)
    float acc[2][16][4];
    const __half* ar;
    auto kbody = [&](int kb) {
        uint4* cur = (kb & 1) ? bfb : bfa;
        uint4* nxt = (kb & 1) ? bfa : bfb;
        ldB(nxt, (kb < 31) ? kb + 1 : 0);          // chains into the next pass

        const int st = kb >> 2;
        const int ko = (kb & 3) * 16 + tg * 4;
        const __half* bps = s_bp + st * 5120 + ko;
        const uint2 ua = *(const uint2*)&ar[kb * 16 + tg * 4];
        const uint2 u0 = *(const uint2*)&bps[(r0     ) * 80];
        const uint2 u1 = *(const uint2*)&bps[(r0 +  8) * 80];
        const uint2 u2 = *(const uint2*)&bps[(r0 + 16) * 80];
        const uint2 u3 = *(const uint2*)&bps[(r0 + 24) * 80];
        uint32_t a0[4], a1[4];
        a0[0] = fragAB(ua.x, u0.x);
        a0[1] = fragAB(ua.x, u1.x);
        a0[2] = fragAB(ua.y, u0.y);
        a0[3] = fragAB(ua.y, u1.y);
        a1[0] = fragAB(ua.x, u2.x);
        a1[1] = fragAB(ua.x, u3.x);
        a1[2] = fragAB(ua.y, u2.y);
        a1[3] = fragAB(ua.y, u3.y);

        #pragma unroll
        for (int q = 0; q < 8; q++) {
            mma_f16(acc[0][2 * q + 0], a0, cur[q].x, cur[q].y);
            mma_f16(acc[0][2 * q + 1], a0, cur[q].z, cur[q].w);
            mma_f16(acc[1][2 * q + 0], a1, cur[q].x, cur[q].y);
            mma_f16(acc[1][2 * q + 1], a1, cur[q].z, cur[q].w);
        }
    };

    auto epilogue = [&](int p) {
        float p0 = 0.0f, p1 = 0.0f, p2s = 0.0f, p3s = 0.0f;
        #pragma unroll
        for (int nt = 0; nt < 16; nt++) {
            const int j = wc * 128 + nt * 8 + 2 * tg;
            const float b2a = s_b2[j], b2b = s_b2[j + 1];
            const float w3a = s_w3[j], w3b = s_w3[j + 1];
            const float* c0 = acc[0][nt];
            const float* c1 = acc[1][nt];
            p0  += fmaxf(c0[0] + b2a, 0.0f) * w3a + fmaxf(c0[1] + b2b, 0.0f) * w3b;
            p1  += fmaxf(c0[2] + b2a, 0.0f) * w3a + fmaxf(c0[3] + b2b, 0.0f) * w3b;
            p2s += fmaxf(c1[0] + b2a, 0.0f) * w3a + fmaxf(c1[1] + b2b, 0.0f) * w3b;
            p3s += fmaxf(c1[2] + b2a, 0.0f) * w3a + fmaxf(c1[3] + b2b, 0.0f) * w3b;
        }
        #pragma unroll
        for (int off = 1; off < 4; off <<= 1) {
            p0  += __shfl_xor_sync(0xffffffffu, p0, off);
            p1  += __shfl_xor_sync(0xffffffffu, p1, off);
            p2s += __shfl_xor_sync(0xffffffffu, p2s, off);
            p3s += __shfl_xor_sync(0xffffffffu, p3s, off);
        }
        float* sp = s_part + (p & 1) * 128;
        if (tg == 0) {
            sp[(r0     ) * 2 + wc] = p0;
            sp[(r0 +  8) * 2 + wc] = p1;
            sp[(r0 + 16) * 2 + wc] = p2s;
            sp[(r0 + 24) * 2 + wc] = p3s;
        }
        __syncthreads();
        if (tid < 64) {
            float v = sp[tid * 2 + 0] + sp[tid * 2 + 1] + b3[0];
            out[(size_t)(n0g + p) * M_DIM + m0 + tid] = v;
        }
    };

    // ---- pass 0: per-stage wait -> overlaps compute with in-flight staging
    #pragma unroll
    for (int mt = 0; mt < 2; mt++)
        #pragma unroll
        for (int nt = 0; nt < 16; nt++)
            #pragma unroll
            for (int q = 0; q < 4; q++) acc[mt][nt][q] = 0.0f;
    ar = s_arow;
    cp_wait<7>(); __syncthreads(); kbody(0);  kbody(1);  kbody(2);  kbody(3);
    cp_wait<6>(); __syncthreads(); kbody(4);  kbody(5);  kbody(6);  kbody(7);
    cp_wait<5>(); __syncthreads(); kbody(8);  kbody(9);  kbody(10); kbody(11);
    cp_wait<4>(); __syncthreads(); kbody(12); kbody(13); kbody(14); kbody(15);
    cp_wait<3>(); __syncthreads(); kbody(16); kbody(17); kbody(18); kbody(19);
    cp_wait<2>(); __syncthreads(); kbody(20); kbody(21); kbody(22); kbody(23);
    cp_wait<1>(); __syncthreads(); kbody(24); kbody(25); kbody(26); kbody(27);
    cp_wait<0>(); __syncthreads(); kbody(28); kbody(29); kbody(30); kbody(31);
    epilogue(0);

    // ---- passes 1..3: everything resident, no waits in the K-loop
    for (int p = 1; p < 4; p++) {
        #pragma unroll
        for (int mt = 0; mt < 2; mt++)
            #pragma unroll
            for (int nt = 0; nt < 16; nt++)
                #pragma unroll
                for (int q = 0; q < 4; q++) acc[mt][nt][q] = 0.0f;
        ar = s_arow + p * 512;
        #pragma unroll 8
        for (int kb = 0; kb < 32; kb++) kbody(kb);
        epilogue(p);
    }
}

// ============================================================================
// Launch
// ============================================================================
extern "C" void kernel_launch(void* const* d_in, const int* in_sizes, int n_in,
                              void* d_out, int out_size) {
    const float* PhiA = (const float*)d_in[0];
    const float* PhiB = (const float*)d_in[1];
    const float* W1a  = (const float*)d_in[2];
    const float* W1b  = (const float*)d_in[3];
    const float* b1   = (const float*)d_in[4];
    const float* W2   = (const float*)d_in[5];
    const float* b2   = (const float*)d_in[6];
    const float* W3   = (const float*)d_in[7];
    const float* b3   = (const float*)d_in[8];
    float* out = (float*)d_out;

    __half* aprojh = nullptr;
    __half* bprojh = nullptr;
    uint4 *w2f = nullptr, *w1af = nullptr, *w1bf = nullptr;
    cudaGetSymbolAddress((void**)&aprojh, g_aprojh);
    cudaGetSymbolAddress((void**)&bprojh, g_bprojh);
    cudaGetSymbolAddress((void**)&w2f, g_w2frag);
    cudaGetSymbolAddress((void**)&w1af, g_w1afrag);
    cudaGetSymbolAddress((void**)&w1bf, g_w1bfrag);

    // fragment all weight matrices (W2, W1a, W1b)
    wfrag_kernel<<<dim3(36, 8, 3), 128>>>(W2, W1a, W1b, w2f, w1af, w1bf);
    // tensor-core projections -> k-permuted fp16 aproj/bproj
    proj_mma_kernel<<<dim3((B_DIM * N_DIM + B_DIM * M_DIM) / 32, H1_DIM / 128), 128>>>(
        PhiA, PhiB, b1, w1af, w1bf, aprojh, bprojh);
    // fused pairwise MLP (4n x 64m tiles, resident bp slab, pipelined prolog)
    cudaFuncSetAttribute(pair_mlp_main, cudaFuncAttributeMaxDynamicSharedMemorySize,
                         SMEM_MAIN);
    pair_mlp_main<<<B_DIM * N_DIM * M_DIM / (4 * 64), 128, SMEM_MAIN>>>(
        aprojh, bprojh, w2f, b2, W3, b3, out);
}